// round 1
// baseline (speedup 1.0000x reference)
#include <cuda_runtime.h>
#include <math.h>

#define BGRAPHS 512
#define MNODES  200
#define EPG     6400
#define ETOT    3276800
#define NTHREADS 256
#define NW 8

// ---- shared memory layout (float slots) ----
#define OFF_HCAT   0          // 200*100
#define OFF_XW     20000      // 200*32
#define OFF_SW     26400      // 4096
#define OFF_NORM   30496      // 6400
#define OFF_DINV   36896      // 200
#define OFF_ROWPTR 37096      // 204 ints
#define OFF_FILL   37300      // 200 ints
#define OFF_DEGI   37500      // 200 ints
#define OFF_CSRSRC 37700      // 6400 u16 -> 3200 slots
#define OFF_SRC16  40900      // 6400 u16 -> 3200 slots (aliased by xstage later)
#define OFF_DST16  44100      // 6400 u16 -> 3200 slots
#define OFF_KEY    47300      // 200
#define OFF_SEL    47500      // 32 ints
#define OFF_C1     47532      // 480
#define OFF_POOL   48012      // 240
#define OFF_FLAT   48252      // 352
#define OFF_HLIN   48604      // 128
#define SMEM_SLOTS 48732
#define SMEM_BYTES (SMEM_SLOTS * 4)

__device__ __forceinline__ float warp_sum(float v) {
    #pragma unroll
    for (int o = 16; o > 0; o >>= 1) v += __shfl_down_sync(0xffffffffu, v, o);
    return v;
}

__global__ __launch_bounds__(NTHREADS, 1)
void dgcnn_kernel(
    const float* __restrict__ x, const int* __restrict__ ei,
    const float* __restrict__ W1, const float* __restrict__ b1,
    const float* __restrict__ W2, const float* __restrict__ b2,
    const float* __restrict__ W3, const float* __restrict__ b3,
    const float* __restrict__ W4, const float* __restrict__ b4,
    const float* __restrict__ convW1, const float* __restrict__ convb1,
    const float* __restrict__ convW2, const float* __restrict__ convb2,
    const float* __restrict__ linW1, const float* __restrict__ linb1,
    const float* __restrict__ linW2, const float* __restrict__ linb2,
    float* __restrict__ out)
{
    extern __shared__ float smem[];
    float* hcat   = smem + OFF_HCAT;    // [200][100]
    float* xw     = smem + OFF_XW;      // [200][32]
    float* sW     = smem + OFF_SW;      // weight staging
    float* normF  = smem + OFF_NORM;    // [6400]
    float* dinv   = smem + OFF_DINV;    // [200]
    int*   rowptr = (int*)(smem + OFF_ROWPTR);
    int*   fill   = (int*)(smem + OFF_FILL);
    int*   degi   = (int*)(smem + OFF_DEGI);
    unsigned short* csrsrc = (unsigned short*)(smem + OFF_CSRSRC);
    unsigned short* src16  = (unsigned short*)(smem + OFF_SRC16);
    unsigned short* dst16  = (unsigned short*)(smem + OFF_DST16);
    float* xstage = smem + OFF_SRC16;   // alias, used after CSR build
    float* sKey   = smem + OFF_KEY;
    int*   sSel   = (int*)(smem + OFF_SEL);
    float* sC1    = smem + OFF_C1;
    float* sPool  = smem + OFF_POOL;
    float* sFlat  = smem + OFF_FLAT;
    float* sHlin  = smem + OFF_HLIN;

    const int g    = blockIdx.x;
    const int tid  = threadIdx.x;
    const int lane = tid & 31;
    const int warp = tid >> 5;
    const int nbase = g * MNODES;
    const long ebase = (long)g * EPG;
    const int* srcg = ei + ebase;
    const int* dstg = ei + (long)ETOT + ebase;

    // ---------------- Phase A: degrees + local edge staging ----------------
    for (int i = tid; i < MNODES; i += NTHREADS) degi[i] = 0;
    __syncthreads();
    for (int i = tid; i < EPG; i += NTHREADS) {
        int s = srcg[i] - nbase;
        int d = dstg[i] - nbase;
        src16[i] = (unsigned short)s;
        dst16[i] = (unsigned short)d;
        atomicAdd(&degi[d], 1);
    }
    __syncthreads();
    for (int i = tid; i < MNODES; i += NTHREADS) {
        dinv[i] = rsqrtf((float)degi[i] + 1.0f);
        fill[i] = 0;
    }
    __syncthreads();
    if (tid == 0) {
        int acc = 0;
        for (int j = 0; j < MNODES; ++j) { rowptr[j] = acc; acc += degi[j]; }
        rowptr[MNODES] = acc;
    }
    __syncthreads();
    // CSR scatter (incoming edges grouped by dst) + edge norms
    for (int i = tid; i < EPG; i += NTHREADS) {
        int d = dst16[i], s = src16[i];
        int pos = rowptr[d] + atomicAdd(&fill[d], 1);
        csrsrc[pos] = (unsigned short)s;
        normF[pos]  = dinv[s] * dinv[d];
    }
    __syncthreads();

    // ---------------- Phase B: layer 1, xw1 = x @ W1 (128 -> 32) ----------------
    for (int i = tid; i < 4096; i += NTHREADS) sW[i] = W1[i];
    for (int i = tid; i < MNODES * 32; i += NTHREADS) xw[i] = 0.0f;
    for (int kt = 0; kt < 8; ++kt) {
        __syncthreads();
        for (int i = tid; i < MNODES * 16; i += NTHREADS) {
            int n = i >> 4, k = i & 15;
            xstage[i] = x[(size_t)(nbase + n) * 128 + kt * 16 + k];
        }
        __syncthreads();
        for (int n = warp; n < MNODES; n += NW) {
            float acc = 0.0f;
            const float* xs = xstage + n * 16;
            const float* wr = sW + kt * 16 * 32 + lane;
            #pragma unroll
            for (int k = 0; k < 16; ++k) acc += xs[k] * wr[k * 32];
            xw[n * 32 + lane] += acc;
        }
    }
    __syncthreads();

    // ---------------- GCN aggregation layers 1-3 (F=32) ----------------
    const float* Bv[3] = { b1, b2, b3 };
    const float* Wv[3] = { W2, W3, (const float*)0 }; // W for NEXT layer's xw
    for (int layer = 0; layer < 3; ++layer) {
        float bl = Bv[layer][lane];
        int off = layer * 32;
        // agg + tanh -> hcat[:, off..off+32)
        for (int n = warp; n < MNODES; n += NW) {
            float dn = dinv[n];
            float acc = xw[n * 32 + lane] * dn * dn;
            int e0 = rowptr[n], e1 = rowptr[n + 1];
            for (int e = e0; e < e1; ++e) {
                int s = (int)csrsrc[e];
                acc += normF[e] * xw[s * 32 + lane];
            }
            hcat[n * 100 + off + lane] = tanhf(acc + bl);
        }
        __syncthreads();
        if (layer < 2) {
            // xw_{l+1} = h_l @ W_{l+1}  (32 -> 32)
            for (int i = tid; i < 1024; i += NTHREADS) sW[i] = Wv[layer][i];
            __syncthreads();
            for (int n = warp; n < MNODES; n += NW) {
                const float* hr = hcat + n * 100 + off;
                float acc = 0.0f;
                #pragma unroll 8
                for (int k = 0; k < 32; ++k) acc += hr[k] * sW[k * 32 + lane];
                xw[n * 32 + lane] = acc;
            }
            __syncthreads();
        }
    }

    // ---------------- Layer 4 (F=1) ----------------
    {
        float w4l = W4[lane];
        for (int n = warp; n < MNODES; n += NW) {
            float v = hcat[n * 100 + 64 + lane] * w4l;
            v = warp_sum(v);
            if (lane == 0) xw[n] = v;   // reuse xw as xw4[200]
        }
        __syncthreads();
        float b4v = b4[0];
        for (int n = tid; n < MNODES; n += NTHREADS) {
            float dn = dinv[n];
            float acc = xw[n] * dn * dn;
            int e1 = rowptr[n + 1];
            for (int e = rowptr[n]; e < e1; ++e)
                acc += normF[e] * xw[(int)csrsrc[e]];
            float h4 = tanhf(acc + b4v);
            hcat[n * 100 + 96] = h4;
            sKey[n] = h4;
        }
        __syncthreads();
    }

    // ---------------- SortPool: stable top-30 by key desc ----------------
    for (int i = tid; i < MNODES; i += NTHREADS) {
        float ki = sKey[i];
        int r = 0;
        for (int j = 0; j < MNODES; ++j) {
            float kj = sKey[j];
            r += (kj > ki) || (kj == ki && j < i);
        }
        if (r < 30) sSel[r] = i;
    }
    // stage conv weights (sW and normF are free now)
    for (int i = tid; i < 16 * 97; i += NTHREADS) sW[i] = convW1[i];
    for (int i = tid; i < 32 * 16 * 5; i += NTHREADS) normF[i] = convW2[i];
    __syncthreads();

    // ---------------- Conv1 (kernel 97, stride 97) -> [16][30], relu ----------------
    for (int it = warp; it < 480; it += NW) {
        int p = it / 16, oc = it % 16;
        int node = sSel[p];
        const float* hr = hcat + node * 100;
        const float* wr = sW + oc * 97;
        float v = hr[lane] * wr[lane] + hr[lane + 32] * wr[lane + 32]
                + hr[lane + 64] * wr[lane + 64];
        if (lane == 0) v += hr[96] * wr[96];
        v = warp_sum(v);
        if (lane == 0) sC1[oc * 30 + p] = fmaxf(v + convb1[oc], 0.0f);
    }
    __syncthreads();

    // ---------------- MaxPool1d(2,2) -> [16][15] ----------------
    for (int i = tid; i < 240; i += NTHREADS) {
        int oc = i / 15, t = i % 15;
        sPool[i] = fmaxf(sC1[oc * 30 + 2 * t], sC1[oc * 30 + 2 * t + 1]);
    }
    __syncthreads();

    // ---------------- Conv2 (16->32, k=5) -> [32][11], relu, flatten ----------------
    for (int it = tid; it < 352; it += NTHREADS) {
        int oc = it / 11, t = it % 11;
        float acc = convb2[oc];
        const float* w = normF + oc * 80;
        #pragma unroll
        for (int ic = 0; ic < 16; ++ic) {
            #pragma unroll
            for (int k = 0; k < 5; ++k)
                acc += w[ic * 5 + k] * sPool[ic * 15 + t + k];
        }
        sFlat[oc * 11 + t] = fmaxf(acc, 0.0f);
    }
    __syncthreads();

    // ---------------- Linear 352->128, relu ----------------
    if (tid < 128) {
        float acc = linb1[tid];
        #pragma unroll 4
        for (int fi = 0; fi < 352; ++fi)
            acc += sFlat[fi] * linW1[fi * 128 + tid];
        sHlin[tid] = fmaxf(acc, 0.0f);
    }
    __syncthreads();

    // ---------------- Linear 128->1, sigmoid ----------------
    if (warp == 0) {
        float acc = 0.0f;
        #pragma unroll
        for (int fi = lane; fi < 128; fi += 32) acc += sHlin[fi] * linW2[fi];
        acc = warp_sum(acc);
        if (lane == 0) {
            float z = acc + linb2[0];
            out[g] = 1.0f / (1.0f + expf(-z));
        }
    }
}

extern "C" void kernel_launch(void* const* d_in, const int* in_sizes, int n_in,
                              void* d_out, int out_size) {
    const float* x      = (const float*)d_in[0];
    const int*   ei     = (const int*)  d_in[1];
    // d_in[2] = batch (structure is implied; unused)
    const float* W1     = (const float*)d_in[3];
    const float* b1     = (const float*)d_in[4];
    const float* W2     = (const float*)d_in[5];
    const float* b2     = (const float*)d_in[6];
    const float* W3     = (const float*)d_in[7];
    const float* b3     = (const float*)d_in[8];
    const float* W4     = (const float*)d_in[9];
    const float* b4     = (const float*)d_in[10];
    const float* convW1 = (const float*)d_in[11];
    const float* convb1 = (const float*)d_in[12];
    const float* convW2 = (const float*)d_in[13];
    const float* convb2 = (const float*)d_in[14];
    const float* linW1  = (const float*)d_in[15];
    const float* linb1  = (const float*)d_in[16];
    const float* linW2  = (const float*)d_in[17];
    const float* linb2  = (const float*)d_in[18];
    float* out = (float*)d_out;

    cudaFuncSetAttribute(dgcnn_kernel,
                         cudaFuncAttributeMaxDynamicSharedMemorySize, SMEM_BYTES);
    dgcnn_kernel<<<BGRAPHS, NTHREADS, SMEM_BYTES>>>(
        x, ei, W1, b1, W2, b2, W3, b3, W4, b4,
        convW1, convb1, convW2, convb2, linW1, linb1, linW2, linb2, out);
}

// round 2
// speedup vs baseline: 1.4567x; 1.4567x over previous
#include <cuda_runtime.h>
#include <math.h>

#define BGRAPHS 512
#define MNODES  200
#define EPG     6400
#define ETOT    3276800
#define NTHREADS 512
#define NW 16

// ---- shared memory layout (float slots) ----
#define OFF_HCAT   0          // 200*100 = 20000
#define OFF_XW     20000      // 200*32  = 6400   (holds dinv-scaled xw)
#define OFF_SW     26400      // 4224 weight/scratch staging
#define OFF_DINV   30624      // 200
#define OFF_ROWPTR 30824      // 204 ints
#define OFF_FILL   31028      // 200 ints
#define OFF_DEGI   31228      // 200 ints
#define OFF_CSRSRC 31428      // 6400 u16 -> 3200 slots
#define OFF_SRC16  34628      // 6400 u16 -> 3200 slots
#define OFF_DST16  37828      // 6400 u16 -> 3200 slots
#define OFF_KEY    41028      // 200
#define OFF_SEL    41228      // 32 ints
#define OFF_C1     41260      // 480
#define OFF_POOL   41740      // 240
#define OFF_FLAT   41980      // 352
#define OFF_HLIN   42332      // 128
#define SMEM_SLOTS 42460
#define SMEM_BYTES (SMEM_SLOTS * 4)

__device__ __forceinline__ float warp_sum(float v) {
    #pragma unroll
    for (int o = 16; o > 0; o >>= 1) v += __shfl_down_sync(0xffffffffu, v, o);
    return v;
}

// tanh via exp2-based __expf: ~8 instrs, abs error ~1e-7 (vs libm ~18 instrs)
__device__ __forceinline__ float fast_tanh(float x) {
    float xc = fminf(fmaxf(x, -15.0f), 15.0f);
    float t = __expf(2.0f * xc);
    return __fdividef(t - 1.0f, t + 1.0f);
}

__global__ __launch_bounds__(NTHREADS, 1)
void dgcnn_kernel(
    const float* __restrict__ x, const int* __restrict__ ei,
    const float* __restrict__ W1, const float* __restrict__ b1,
    const float* __restrict__ W2, const float* __restrict__ b2,
    const float* __restrict__ W3, const float* __restrict__ b3,
    const float* __restrict__ W4, const float* __restrict__ b4,
    const float* __restrict__ convW1, const float* __restrict__ convb1,
    const float* __restrict__ convW2, const float* __restrict__ convb2,
    const float* __restrict__ linW1, const float* __restrict__ linb1,
    const float* __restrict__ linW2, const float* __restrict__ linb2,
    float* __restrict__ out)
{
    extern __shared__ float smem[];
    float* hcat   = smem + OFF_HCAT;    // [200][100]
    float* xw     = smem + OFF_XW;      // [200][32] (dinv-scaled)
    float* sW     = smem + OFF_SW;      // weight staging / scratch
    float* dinv   = smem + OFF_DINV;
    int*   rowptr = (int*)(smem + OFF_ROWPTR);
    int*   fill   = (int*)(smem + OFF_FILL);
    int*   degi   = (int*)(smem + OFF_DEGI);
    unsigned short* csrsrc = (unsigned short*)(smem + OFF_CSRSRC);
    unsigned short* src16  = (unsigned short*)(smem + OFF_SRC16);
    unsigned short* dst16  = (unsigned short*)(smem + OFF_DST16);
    float* sKey   = smem + OFF_KEY;
    int*   sSel   = (int*)(smem + OFF_SEL);
    float* sC1    = smem + OFF_C1;
    float* sPool  = smem + OFF_POOL;
    float* sFlat  = smem + OFF_FLAT;
    float* sHlin  = smem + OFF_HLIN;

    const int g    = blockIdx.x;
    const int tid  = threadIdx.x;
    const int lane = tid & 31;
    const int warp = tid >> 5;
    const int nbase = g * MNODES;
    const long ebase = (long)g * EPG;
    const int* srcg = ei + ebase;
    const int* dstg = ei + (long)ETOT + ebase;

    // ---------------- Phase A: degrees + local edge staging (vectorized) ----------------
    for (int i = tid; i < MNODES; i += NTHREADS) degi[i] = 0;
    __syncthreads();
    for (int i = tid; i < EPG / 4; i += NTHREADS) {
        int4 s4 = ((const int4*)srcg)[i];
        int4 d4 = ((const int4*)dstg)[i];
        ushort4 ss, dd;
        ss.x = (unsigned short)(s4.x - nbase); ss.y = (unsigned short)(s4.y - nbase);
        ss.z = (unsigned short)(s4.z - nbase); ss.w = (unsigned short)(s4.w - nbase);
        dd.x = (unsigned short)(d4.x - nbase); dd.y = (unsigned short)(d4.y - nbase);
        dd.z = (unsigned short)(d4.z - nbase); dd.w = (unsigned short)(d4.w - nbase);
        ((ushort4*)src16)[i] = ss;
        ((ushort4*)dst16)[i] = dd;
        atomicAdd(&degi[dd.x], 1); atomicAdd(&degi[dd.y], 1);
        atomicAdd(&degi[dd.z], 1); atomicAdd(&degi[dd.w], 1);
    }
    __syncthreads();
    for (int i = tid; i < MNODES; i += NTHREADS) {
        dinv[i] = rsqrtf((float)degi[i] + 1.0f);
        fill[i] = 0;
    }
    // warp-shuffle exclusive scan of degrees -> rowptr (warp 0 only)
    if (warp == 0) {
        int run = 0;
        #pragma unroll
        for (int c = 0; c < 7; ++c) {
            int i = c * 32 + lane;
            int dv = (i < MNODES) ? degi[i] : 0;
            int v = dv;
            #pragma unroll
            for (int o = 1; o < 32; o <<= 1) {
                int t = __shfl_up_sync(0xffffffffu, v, o);
                if (lane >= o) v += t;
            }
            if (i < MNODES) rowptr[i] = run + v - dv;
            run += __shfl_sync(0xffffffffu, v, 31);
        }
        if (lane == 0) rowptr[MNODES] = EPG;
    }
    __syncthreads();
    // CSR scatter (incoming edges grouped by dst); stage W1 concurrently
    for (int i = tid; i < EPG; i += NTHREADS) {
        int d = dst16[i];
        int pos = rowptr[d] + atomicAdd(&fill[d], 1);
        csrsrc[pos] = src16[i];
    }
    for (int i = tid; i < 4096; i += NTHREADS) sW[i] = W1[i];
    __syncthreads();

    // ---------------- Phase B: xw1 = dinv * (x @ W1) (128 -> 32), shuffle-based ----------------
    for (int n = warp; n < MNODES; n += NW) {
        const float4 rx = *(const float4*)(x + (size_t)(nbase + n) * 128 + lane * 4);
        float acc0 = 0.0f, acc1 = 0.0f;
        #pragma unroll
        for (int k4 = 0; k4 < 32; ++k4) {
            float x0 = __shfl_sync(0xffffffffu, rx.x, k4);
            float x1 = __shfl_sync(0xffffffffu, rx.y, k4);
            float x2 = __shfl_sync(0xffffffffu, rx.z, k4);
            float x3 = __shfl_sync(0xffffffffu, rx.w, k4);
            const float* wr = sW + k4 * 128 + lane;
            acc0 += x0 * wr[0];
            acc1 += x1 * wr[32];
            acc0 += x2 * wr[64];
            acc1 += x3 * wr[96];
        }
        xw[n * 32 + lane] = dinv[n] * (acc0 + acc1);
    }
    __syncthreads();

    // ---------------- GCN aggregation layers 1-3 (F=32) ----------------
    const float* Bv[3] = { b1, b2, b3 };
    const float* Wv[2] = { W2, W3 };
    for (int layer = 0; layer < 3; ++layer) {
        float bl = Bv[layer][lane];
        int off = layer * 32;
        // agg = dinv[n] * (xwd[n] + sum_e xwd[src]); tanh -> hcat
        for (int n = warp; n < MNODES; n += NW) {
            int e0 = rowptr[n], e1 = rowptr[n + 1];
            float acc0 = xw[n * 32 + lane];
            float acc1 = 0.0f, acc2 = 0.0f, acc3 = 0.0f;
            int e = e0;
            for (; e + 4 <= e1; e += 4) {
                int s0 = csrsrc[e],     s1 = csrsrc[e + 1];
                int s2 = csrsrc[e + 2], s3 = csrsrc[e + 3];
                acc0 += xw[s0 * 32 + lane];
                acc1 += xw[s1 * 32 + lane];
                acc2 += xw[s2 * 32 + lane];
                acc3 += xw[s3 * 32 + lane];
            }
            for (; e < e1; ++e) acc1 += xw[(int)csrsrc[e] * 32 + lane];
            float aggv = dinv[n] * ((acc0 + acc2) + (acc1 + acc3));
            hcat[n * 100 + off + lane] = fast_tanh(aggv + bl);
        }
        if (layer < 2) {
            for (int i = tid; i < 1024; i += NTHREADS) sW[i] = Wv[layer][i];
            __syncthreads();
            // xw_{l+1} = dinv * (h_l @ W_{l+1})
            for (int n = warp; n < MNODES; n += NW) {
                const float* hr = hcat + n * 100 + off;
                float acc0 = 0.0f, acc1 = 0.0f;
                #pragma unroll
                for (int k = 0; k < 32; k += 2) {
                    acc0 += hr[k]     * sW[k * 32 + lane];
                    acc1 += hr[k + 1] * sW[(k + 1) * 32 + lane];
                }
                xw[n * 32 + lane] = dinv[n] * (acc0 + acc1);
            }
            __syncthreads();
        } else {
            __syncthreads();
        }
    }

    // ---------------- Layer 4 (F=1) ----------------
    {
        float w4l = W4[lane];
        for (int n = warp; n < MNODES; n += NW) {
            float v = hcat[n * 100 + 64 + lane] * w4l;
            v = warp_sum(v);
            if (lane == 0) xw[n] = dinv[n] * v;   // xwd4[200]
        }
        __syncthreads();
        float b4v = b4[0];
        for (int n = tid; n < MNODES; n += NTHREADS) {
            float acc = xw[n];
            int e1 = rowptr[n + 1];
            for (int e = rowptr[n]; e < e1; ++e)
                acc += xw[(int)csrsrc[e]];
            float h4 = fast_tanh(dinv[n] * acc + b4v);
            hcat[n * 100 + 96] = h4;
            sKey[n] = h4;
        }
        __syncthreads();
    }

    // ---------------- SortPool: stable top-30 by key desc ----------------
    for (int i = tid; i < MNODES; i += NTHREADS) {
        float ki = sKey[i];
        int r = 0;
        for (int j = 0; j < MNODES; ++j) {
            float kj = sKey[j];
            r += (kj > ki) || (kj == ki && j < i);
        }
        if (r < 30) sSel[r] = i;
    }
    // stage conv weights into sW (free after last GEMM)
    for (int i = tid; i < 16 * 97; i += NTHREADS) sW[i] = convW1[i];
    for (int i = tid; i < 32 * 16 * 5; i += NTHREADS) sW[1552 + i] = convW2[i];
    __syncthreads();

    // ---------------- Conv1 (kernel 97, stride 97) -> [16][30], relu ----------------
    for (int it = warp; it < 480; it += NW) {
        int p = it / 16, oc = it % 16;
        int node = sSel[p];
        const float* hr = hcat + node * 100;
        const float* wr = sW + oc * 97;
        float v = hr[lane] * wr[lane] + hr[lane + 32] * wr[lane + 32]
                + hr[lane + 64] * wr[lane + 64];
        if (lane == 0) v += hr[96] * wr[96];
        v = warp_sum(v);
        if (lane == 0) sC1[oc * 30 + p] = fmaxf(v + convb1[oc], 0.0f);
    }
    __syncthreads();

    // ---------------- MaxPool1d(2,2) -> [16][15] ----------------
    for (int i = tid; i < 240; i += NTHREADS) {
        int oc = i / 15, t = i % 15;
        sPool[i] = fmaxf(sC1[oc * 30 + 2 * t], sC1[oc * 30 + 2 * t + 1]);
    }
    __syncthreads();

    // ---------------- Conv2 (16->32, k=5) -> [32][11], relu, flatten ----------------
    for (int it = tid; it < 352; it += NTHREADS) {
        int oc = it / 11, t = it % 11;
        float acc = convb2[oc];
        const float* w = sW + 1552 + oc * 80;
        #pragma unroll
        for (int ic = 0; ic < 16; ++ic) {
            #pragma unroll
            for (int k = 0; k < 5; ++k)
                acc += w[ic * 5 + k] * sPool[ic * 15 + t + k];
        }
        sFlat[oc * 11 + t] = fmaxf(acc, 0.0f);
    }
    __syncthreads();

    // ---------------- Linear 352->128 (split-K over 4 groups), relu ----------------
    {
        int grp = tid >> 7, t = tid & 127;
        float acc = 0.0f;
        int f0 = grp * 88, f1 = f0 + 88;
        for (int fi = f0; fi < f1; ++fi)
            acc += sFlat[fi] * linW1[fi * 128 + t];
        sW[grp * 128 + t] = acc;    // sW reused as partial buffer
    }
    __syncthreads();
    if (tid < 128) {
        float a = linb1[tid] + sW[tid] + sW[128 + tid] + sW[256 + tid] + sW[384 + tid];
        sHlin[tid] = fmaxf(a, 0.0f);
    }
    __syncthreads();

    // ---------------- Linear 128->1, sigmoid ----------------
    if (warp == 0) {
        float acc = sHlin[lane] * linW2[lane] + sHlin[lane + 32] * linW2[lane + 32]
                  + sHlin[lane + 64] * linW2[lane + 64] + sHlin[lane + 96] * linW2[lane + 96];
        acc = warp_sum(acc);
        if (lane == 0) {
            float z = acc + linb2[0];
            out[g] = __fdividef(1.0f, 1.0f + __expf(-z));
        }
    }
}

extern "C" void kernel_launch(void* const* d_in, const int* in_sizes, int n_in,
                              void* d_out, int out_size) {
    const float* x      = (const float*)d_in[0];
    const int*   ei     = (const int*)  d_in[1];
    const float* W1     = (const float*)d_in[3];
    const float* b1     = (const float*)d_in[4];
    const float* W2     = (const float*)d_in[5];
    const float* b2     = (const float*)d_in[6];
    const float* W3     = (const float*)d_in[7];
    const float* b3     = (const float*)d_in[8];
    const float* W4     = (const float*)d_in[9];
    const float* b4     = (const float*)d_in[10];
    const float* convW1 = (const float*)d_in[11];
    const float* convb1 = (const float*)d_in[12];
    const float* convW2 = (const float*)d_in[13];
    const float* convb2 = (const float*)d_in[14];
    const float* linW1  = (const float*)d_in[15];
    const float* linb1  = (const float*)d_in[16];
    const float* linW2  = (const float*)d_in[17];
    const float* linb2  = (const float*)d_in[18];
    float* out = (float*)d_out;

    cudaFuncSetAttribute(dgcnn_kernel,
                         cudaFuncAttributeMaxDynamicSharedMemorySize, SMEM_BYTES);
    dgcnn_kernel<<<BGRAPHS, NTHREADS, SMEM_BYTES>>>(
        x, ei, W1, b1, W2, b2, W3, b3, W4, b4,
        convW1, convb1, convW2, convb2, linW1, linb1, linW2, linb2, out);
}

// round 3
// speedup vs baseline: 1.7495x; 1.2010x over previous
#include <cuda_runtime.h>
#include <math.h>

#define BGRAPHS 512
#define MNODES  200
#define EPG     6400
#define ETOT    3276800
#define NTHREADS 1024
#define NW 32

// ---- shared memory layout (float slots) ----
#define OFF_HCAT   0          // 200*100 = 20000
#define OFF_XW     20000      // 200*32  = 6400   (holds dinv-scaled xw)
#define OFF_SW     26400      // 4224 weight/scratch staging
#define OFF_DINV   30624      // 200
#define OFF_ROWPTR 30824      // 204 ints
#define OFF_FILL   31028      // 200 ints
#define OFF_DEGI   31228      // 200 ints
#define OFF_CSRSRC 31428      // 6400 u16 -> 3200 slots
#define OFF_SRC16  34628      // 6400 u16 -> 3200 slots
#define OFF_DST16  37828      // 6400 u16 -> 3200 slots
#define OFF_KEY    41028      // 200
#define OFF_SEL    41228      // 32 ints
#define OFF_C1     41260      // 480
#define OFF_POOL   41740      // 240
#define OFF_FLAT   41980      // 352
#define OFF_HLIN   42332      // 128
#define SMEM_SLOTS 42460
#define SMEM_BYTES (SMEM_SLOTS * 4)

__device__ __forceinline__ float warp_sum(float v) {
    #pragma unroll
    for (int o = 16; o > 0; o >>= 1) v += __shfl_down_sync(0xffffffffu, v, o);
    return v;
}

// tanh via __expf: ~8 instrs, abs error ~1e-7
__device__ __forceinline__ float fast_tanh(float x) {
    float xc = fminf(fmaxf(x, -15.0f), 15.0f);
    float t = __expf(2.0f * xc);
    return __fdividef(t - 1.0f, t + 1.0f);
}

__global__ __launch_bounds__(NTHREADS, 1)
void dgcnn_kernel(
    const float* __restrict__ x, const int* __restrict__ ei,
    const float* __restrict__ W1, const float* __restrict__ b1,
    const float* __restrict__ W2, const float* __restrict__ b2,
    const float* __restrict__ W3, const float* __restrict__ b3,
    const float* __restrict__ W4, const float* __restrict__ b4,
    const float* __restrict__ convW1, const float* __restrict__ convb1,
    const float* __restrict__ convW2, const float* __restrict__ convb2,
    const float* __restrict__ linW1, const float* __restrict__ linb1,
    const float* __restrict__ linW2, const float* __restrict__ linb2,
    float* __restrict__ out)
{
    extern __shared__ float smem[];
    float* hcat   = smem + OFF_HCAT;    // [200][100]
    float* xw     = smem + OFF_XW;      // [200][32] (dinv-scaled)
    float* sW     = smem + OFF_SW;      // weight staging / scratch
    float* dinv   = smem + OFF_DINV;
    int*   rowptr = (int*)(smem + OFF_ROWPTR);
    int*   fill   = (int*)(smem + OFF_FILL);
    int*   degi   = (int*)(smem + OFF_DEGI);
    unsigned short* csrsrc = (unsigned short*)(smem + OFF_CSRSRC);
    unsigned short* src16  = (unsigned short*)(smem + OFF_SRC16);
    unsigned short* dst16  = (unsigned short*)(smem + OFF_DST16);
    float* sKey   = smem + OFF_KEY;
    int*   sSel   = (int*)(smem + OFF_SEL);
    float* sC1    = smem + OFF_C1;
    float* sPool  = smem + OFF_POOL;
    float* sFlat  = smem + OFF_FLAT;
    float* sHlin  = smem + OFF_HLIN;

    const int g    = blockIdx.x;
    const int tid  = threadIdx.x;
    const int lane = tid & 31;
    const int warp = tid >> 5;
    const int nbase = g * MNODES;
    const long ebase = (long)g * EPG;
    const int* srcg = ei + ebase;
    const int* dstg = ei + (long)ETOT + ebase;

    // ---------------- Phase A: degrees + local edge staging (vectorized) ----------------
    for (int i = tid; i < MNODES; i += NTHREADS) degi[i] = 0;
    __syncthreads();
    for (int i = tid; i < EPG / 4; i += NTHREADS) {
        int4 s4 = ((const int4*)srcg)[i];
        int4 d4 = ((const int4*)dstg)[i];
        ushort4 ss, dd;
        ss.x = (unsigned short)(s4.x - nbase); ss.y = (unsigned short)(s4.y - nbase);
        ss.z = (unsigned short)(s4.z - nbase); ss.w = (unsigned short)(s4.w - nbase);
        dd.x = (unsigned short)(d4.x - nbase); dd.y = (unsigned short)(d4.y - nbase);
        dd.z = (unsigned short)(d4.z - nbase); dd.w = (unsigned short)(d4.w - nbase);
        ((ushort4*)src16)[i] = ss;
        ((ushort4*)dst16)[i] = dd;
        atomicAdd(&degi[dd.x], 1); atomicAdd(&degi[dd.y], 1);
        atomicAdd(&degi[dd.z], 1); atomicAdd(&degi[dd.w], 1);
    }
    __syncthreads();
    for (int i = tid; i < MNODES; i += NTHREADS) {
        dinv[i] = rsqrtf((float)degi[i] + 1.0f);
        fill[i] = 0;
    }
    // warp-shuffle exclusive scan of degrees -> rowptr (warp 0 only)
    if (warp == 0) {
        int run = 0;
        #pragma unroll
        for (int c = 0; c < 7; ++c) {
            int i = c * 32 + lane;
            int dv = (i < MNODES) ? degi[i] : 0;
            int v = dv;
            #pragma unroll
            for (int o = 1; o < 32; o <<= 1) {
                int t = __shfl_up_sync(0xffffffffu, v, o);
                if (lane >= o) v += t;
            }
            if (i < MNODES) rowptr[i] = run + v - dv;
            run += __shfl_sync(0xffffffffu, v, 31);
        }
        if (lane == 0) rowptr[MNODES] = EPG;
    }
    __syncthreads();
    // CSR scatter (incoming edges grouped by dst); stage W1 concurrently
    for (int i = tid; i < EPG; i += NTHREADS) {
        int d = dst16[i];
        int pos = rowptr[d] + atomicAdd(&fill[d], 1);
        csrsrc[pos] = src16[i];
    }
    for (int i = tid; i < 4096; i += NTHREADS) sW[i] = W1[i];
    __syncthreads();

    // ---------------- Phase B: xw1 = dinv * (x @ W1), 2 nodes per warp iter ----------------
    for (int n0 = warp * 2; n0 < MNODES; n0 += NW * 2) {
        int n1 = n0 + 1;   // MNODES even -> always valid
        const float4 ra = *(const float4*)(x + (size_t)(nbase + n0) * 128 + lane * 4);
        const float4 rb = *(const float4*)(x + (size_t)(nbase + n1) * 128 + lane * 4);
        float a0 = 0.0f, a1 = 0.0f, c0 = 0.0f, c1 = 0.0f;
        #pragma unroll
        for (int k4 = 0; k4 < 32; ++k4) {
            const float* wr = sW + k4 * 128 + lane;
            float w0 = wr[0], w1 = wr[32], w2 = wr[64], w3 = wr[96];
            a0 += __shfl_sync(0xffffffffu, ra.x, k4) * w0;
            a1 += __shfl_sync(0xffffffffu, ra.y, k4) * w1;
            a0 += __shfl_sync(0xffffffffu, ra.z, k4) * w2;
            a1 += __shfl_sync(0xffffffffu, ra.w, k4) * w3;
            c0 += __shfl_sync(0xffffffffu, rb.x, k4) * w0;
            c1 += __shfl_sync(0xffffffffu, rb.y, k4) * w1;
            c0 += __shfl_sync(0xffffffffu, rb.z, k4) * w2;
            c1 += __shfl_sync(0xffffffffu, rb.w, k4) * w3;
        }
        xw[n0 * 32 + lane] = dinv[n0] * (a0 + a1);
        xw[n1 * 32 + lane] = dinv[n1] * (c0 + c1);
    }
    __syncthreads();

    // ---------------- GCN aggregation layers 1-3 (F=32) ----------------
    const float* Bv[3] = { b1, b2, b3 };
    const float* Wv[2] = { W2, W3 };
    for (int layer = 0; layer < 3; ++layer) {
        float bl = Bv[layer][lane];
        int off = layer * 32;
        for (int n = warp; n < MNODES; n += NW) {
            int e0 = rowptr[n], e1 = rowptr[n + 1];
            float acc0 = xw[n * 32 + lane];
            float acc1 = 0.0f, acc2 = 0.0f, acc3 = 0.0f;
            int e = e0;
            for (; e + 4 <= e1; e += 4) {
                int s0 = csrsrc[e],     s1 = csrsrc[e + 1];
                int s2 = csrsrc[e + 2], s3 = csrsrc[e + 3];
                acc0 += xw[s0 * 32 + lane];
                acc1 += xw[s1 * 32 + lane];
                acc2 += xw[s2 * 32 + lane];
                acc3 += xw[s3 * 32 + lane];
            }
            for (; e < e1; ++e) acc1 += xw[(int)csrsrc[e] * 32 + lane];
            float aggv = dinv[n] * ((acc0 + acc2) + (acc1 + acc3));
            hcat[n * 100 + off + lane] = fast_tanh(aggv + bl);
        }
        if (layer < 2) {
            for (int i = tid; i < 1024; i += NTHREADS) sW[i] = Wv[layer][i];
            __syncthreads();
            for (int n = warp; n < MNODES; n += NW) {
                const float* hr = hcat + n * 100 + off;
                float acc0 = 0.0f, acc1 = 0.0f;
                #pragma unroll
                for (int k = 0; k < 32; k += 2) {
                    acc0 += hr[k]     * sW[k * 32 + lane];
                    acc1 += hr[k + 1] * sW[(k + 1) * 32 + lane];
                }
                xw[n * 32 + lane] = dinv[n] * (acc0 + acc1);
            }
            __syncthreads();
        } else {
            __syncthreads();
        }
    }

    // ---------------- Layer 4 (F=1) ----------------
    {
        float w4l = W4[lane];
        for (int n = warp; n < MNODES; n += NW) {
            float v = hcat[n * 100 + 64 + lane] * w4l;
            v = warp_sum(v);
            if (lane == 0) xw[n] = dinv[n] * v;   // xwd4[200]
        }
        __syncthreads();
        float b4v = b4[0];
        for (int n = tid; n < MNODES; n += NTHREADS) {
            float acc = xw[n];
            int e1 = rowptr[n + 1];
            for (int e = rowptr[n]; e < e1; ++e)
                acc += xw[(int)csrsrc[e]];
            float h4 = fast_tanh(dinv[n] * acc + b4v);
            hcat[n * 100 + 96] = h4;
            sKey[n] = h4;
        }
        __syncthreads();
    }

    // ---------------- SortPool: stable top-30 by key desc ----------------
    for (int i = tid; i < MNODES; i += NTHREADS) {
        float ki = sKey[i];
        int r = 0;
        for (int j = 0; j < MNODES; ++j) {
            float kj = sKey[j];
            r += (kj > ki) || (kj == ki && j < i);
        }
        if (r < 30) sSel[r] = i;
    }
    // stage conv weights into sW (free after last GEMM)
    for (int i = tid; i < 16 * 97; i += NTHREADS) sW[i] = convW1[i];
    for (int i = tid; i < 32 * 16 * 5; i += NTHREADS) sW[1552 + i] = convW2[i];
    __syncthreads();

    // ---------------- Conv1 (kernel 97, stride 97) -> [16][30], relu ----------------
    for (int it = warp; it < 480; it += NW) {
        int p = it / 16, oc = it % 16;
        int node = sSel[p];
        const float* hr = hcat + node * 100;
        const float* wr = sW + oc * 97;
        float v = hr[lane] * wr[lane] + hr[lane + 32] * wr[lane + 32]
                + hr[lane + 64] * wr[lane + 64];
        if (lane == 0) v += hr[96] * wr[96];
        v = warp_sum(v);
        if (lane == 0) sC1[oc * 30 + p] = fmaxf(v + convb1[oc], 0.0f);
    }
    __syncthreads();

    // ---------------- MaxPool1d(2,2) -> [16][15] ----------------
    for (int i = tid; i < 240; i += NTHREADS) {
        int oc = i / 15, t = i % 15;
        sPool[i] = fmaxf(sC1[oc * 30 + 2 * t], sC1[oc * 30 + 2 * t + 1]);
    }
    __syncthreads();

    // ---------------- Conv2 (16->32, k=5) -> [32][11], relu, flatten ----------------
    for (int it = tid; it < 352; it += NTHREADS) {
        int oc = it / 11, t = it % 11;
        float acc = convb2[oc];
        const float* w = sW + 1552 + oc * 80;
        #pragma unroll
        for (int ic = 0; ic < 16; ++ic) {
            #pragma unroll
            for (int k = 0; k < 5; ++k)
                acc += w[ic * 5 + k] * sPool[ic * 15 + t + k];
        }
        sFlat[oc * 11 + t] = fmaxf(acc, 0.0f);
    }
    __syncthreads();

    // ---------------- Linear 352->128 (split-K over 8 groups), relu ----------------
    {
        int grp = tid >> 7, t = tid & 127;
        float acc = 0.0f;
        int f0 = grp * 44, f1 = f0 + 44;
        for (int fi = f0; fi < f1; ++fi)
            acc += sFlat[fi] * linW1[fi * 128 + t];
        sW[grp * 128 + t] = acc;    // sW reused as partial buffer
    }
    __syncthreads();
    if (tid < 128) {
        float a = linb1[tid];
        #pragma unroll
        for (int grp = 0; grp < 8; ++grp) a += sW[grp * 128 + tid];
        sHlin[tid] = fmaxf(a, 0.0f);
    }
    __syncthreads();

    // ---------------- Linear 128->1, sigmoid ----------------
    if (warp == 0) {
        float acc = sHlin[lane] * linW2[lane] + sHlin[lane + 32] * linW2[lane + 32]
                  + sHlin[lane + 64] * linW2[lane + 64] + sHlin[lane + 96] * linW2[lane + 96];
        acc = warp_sum(acc);
        if (lane == 0) {
            float z = acc + linb2[0];
            out[g] = __fdividef(1.0f, 1.0f + __expf(-z));
        }
    }
}

extern "C" void kernel_launch(void* const* d_in, const int* in_sizes, int n_in,
                              void* d_out, int out_size) {
    const float* x      = (const float*)d_in[0];
    const int*   ei     = (const int*)  d_in[1];
    const float* W1     = (const float*)d_in[3];
    const float* b1     = (const float*)d_in[4];
    const float* W2     = (const float*)d_in[5];
    const float* b2     = (const float*)d_in[6];
    const float* W3     = (const float*)d_in[7];
    const float* b3     = (const float*)d_in[8];
    const float* W4     = (const float*)d_in[9];
    const float* b4     = (const float*)d_in[10];
    const float* convW1 = (const float*)d_in[11];
    const float* convb1 = (const float*)d_in[12];
    const float* convW2 = (const float*)d_in[13];
    const float* convb2 = (const float*)d_in[14];
    const float* linW1  = (const float*)d_in[15];
    const float* linb1  = (const float*)d_in[16];
    const float* linW2  = (const float*)d_in[17];
    const float* linb2  = (const float*)d_in[18];
    float* out = (float*)d_out;

    cudaFuncSetAttribute(dgcnn_kernel,
                         cudaFuncAttributeMaxDynamicSharedMemorySize, SMEM_BYTES);
    dgcnn_kernel<<<BGRAPHS, NTHREADS, SMEM_BYTES>>>(
        x, ei, W1, b1, W2, b2, W3, b3, W4, b4,
        convW1, convb1, convW2, convb2, linW1, linb1, linW2, linb2, out);
}

// round 4
// speedup vs baseline: 1.7762x; 1.0152x over previous
#include <cuda_runtime.h>
#include <math.h>

#define BGRAPHS 512
#define MNODES  200
#define EPG     6400
#define ETOT    3276800
#define NTHREADS 1024
#define NW 32

// ---- shared memory layout (float slots) ----
#define OFF_HCAT   0          // 200*100 = 20000 (also x@W1 per-warp scratch early)
#define OFF_XW     20000      // 200*32  = 6400   (holds dinv-scaled xw)
#define OFF_SW     26400      // 4224 weight/scratch staging (W1^T = 32*132)
#define OFF_DINV   30624      // 200
#define OFF_ROWPTR 30824      // 204 ints
#define OFF_FILL   31028      // 200 ints
#define OFF_DEGI   31228      // 200 ints
#define OFF_CSRSRC 31428      // 6400 u16 -> 3200 slots
#define OFF_SRC16  34628      // 6400 u16 -> 3200 slots
#define OFF_DST16  37828      // 6400 u16 -> 3200 slots
#define OFF_KEY    41028      // 200
#define OFF_SEL    41228      // 32 ints
#define OFF_C1     41260      // 480
#define OFF_POOL   41740      // 240
#define OFF_FLAT   41980      // 352
#define OFF_HLIN   42332      // 128
#define SMEM_SLOTS 42460
#define SMEM_BYTES (SMEM_SLOTS * 4)

typedef unsigned long long u64;

__device__ __forceinline__ u64 fma2(u64 a, u64 b, u64 c) {
    u64 d; asm("fma.rn.f32x2 %0,%1,%2,%3;" : "=l"(d) : "l"(a), "l"(b), "l"(c)); return d;
}
__device__ __forceinline__ u64 add2(u64 a, u64 b) {
    u64 d; asm("add.rn.f32x2 %0,%1,%2;" : "=l"(d) : "l"(a), "l"(b)); return d;
}
__device__ __forceinline__ float2 u2f(u64 a) {
    float2 f; asm("mov.b64 {%0,%1},%2;" : "=f"(f.x), "=f"(f.y) : "l"(a)); return f;
}

__device__ __forceinline__ float warp_sum(float v) {
    #pragma unroll
    for (int o = 16; o > 0; o >>= 1) v += __shfl_down_sync(0xffffffffu, v, o);
    return v;
}

// tanh via __expf: ~8 instrs, abs error ~1e-7
__device__ __forceinline__ float fast_tanh(float x) {
    float xc = fminf(fmaxf(x, -15.0f), 15.0f);
    float t = __expf(2.0f * xc);
    return __fdividef(t - 1.0f, t + 1.0f);
}

__global__ __launch_bounds__(NTHREADS, 1)
void dgcnn_kernel(
    const float* __restrict__ x, const int* __restrict__ ei,
    const float* __restrict__ W1, const float* __restrict__ b1,
    const float* __restrict__ W2, const float* __restrict__ b2,
    const float* __restrict__ W3, const float* __restrict__ b3,
    const float* __restrict__ W4, const float* __restrict__ b4,
    const float* __restrict__ convW1, const float* __restrict__ convb1,
    const float* __restrict__ convW2, const float* __restrict__ convb2,
    const float* __restrict__ linW1, const float* __restrict__ linb1,
    const float* __restrict__ linW2, const float* __restrict__ linb2,
    float* __restrict__ out)
{
    extern __shared__ float smem[];
    float* hcat   = smem + OFF_HCAT;    // [200][100]
    float* xw     = smem + OFF_XW;      // [200][32] (dinv-scaled)
    float* sW     = smem + OFF_SW;      // transposed weight staging / scratch
    float* dinv   = smem + OFF_DINV;
    int*   rowptr = (int*)(smem + OFF_ROWPTR);
    int*   fill   = (int*)(smem + OFF_FILL);
    int*   degi   = (int*)(smem + OFF_DEGI);
    unsigned short* csrsrc = (unsigned short*)(smem + OFF_CSRSRC);
    unsigned short* src16  = (unsigned short*)(smem + OFF_SRC16);
    unsigned short* dst16  = (unsigned short*)(smem + OFF_DST16);
    float* sKey   = smem + OFF_KEY;
    int*   sSel   = (int*)(smem + OFF_SEL);
    float* sC1    = smem + OFF_C1;
    float* sPool  = smem + OFF_POOL;
    float* sFlat  = smem + OFF_FLAT;
    float* sHlin  = smem + OFF_HLIN;

    const int g    = blockIdx.x;
    const int tid  = threadIdx.x;
    const int lane = tid & 31;
    const int warp = tid >> 5;
    const int half = lane >> 4;      // 0/1: which node of the pair
    const int hl   = lane & 15;      // feature-pair index within node
    const int nbase = g * MNODES;
    const long ebase = (long)g * EPG;
    const int* srcg = ei + ebase;
    const int* dstg = ei + (long)ETOT + ebase;

    // ---------------- Phase A: degrees + local edge staging (vectorized) ----------------
    for (int i = tid; i < MNODES; i += NTHREADS) degi[i] = 0;
    __syncthreads();
    for (int i = tid; i < EPG / 4; i += NTHREADS) {
        int4 s4 = ((const int4*)srcg)[i];
        int4 d4 = ((const int4*)dstg)[i];
        ushort4 ss, dd;
        ss.x = (unsigned short)(s4.x - nbase); ss.y = (unsigned short)(s4.y - nbase);
        ss.z = (unsigned short)(s4.z - nbase); ss.w = (unsigned short)(s4.w - nbase);
        dd.x = (unsigned short)(d4.x - nbase); dd.y = (unsigned short)(d4.y - nbase);
        dd.z = (unsigned short)(d4.z - nbase); dd.w = (unsigned short)(d4.w - nbase);
        ((ushort4*)src16)[i] = ss;
        ((ushort4*)dst16)[i] = dd;
        atomicAdd(&degi[dd.x], 1); atomicAdd(&degi[dd.y], 1);
        atomicAdd(&degi[dd.z], 1); atomicAdd(&degi[dd.w], 1);
    }
    __syncthreads();
    for (int i = tid; i < MNODES; i += NTHREADS) {
        dinv[i] = rsqrtf((float)degi[i] + 1.0f);
        fill[i] = 0;
    }
    // warp-shuffle exclusive scan of degrees -> rowptr (warp 0 only)
    if (warp == 0) {
        int run = 0;
        #pragma unroll
        for (int c = 0; c < 7; ++c) {
            int i = c * 32 + lane;
            int dv = (i < MNODES) ? degi[i] : 0;
            int v = dv;
            #pragma unroll
            for (int o = 1; o < 32; o <<= 1) {
                int t = __shfl_up_sync(0xffffffffu, v, o);
                if (lane >= o) v += t;
            }
            if (i < MNODES) rowptr[i] = run + v - dv;
            run += __shfl_sync(0xffffffffu, v, 31);
        }
        if (lane == 0) rowptr[MNODES] = EPG;
    }
    __syncthreads();
    // CSR scatter; stage W1^T concurrently: sW[c*132 + k] = W1[k*32 + c]
    for (int i = tid; i < EPG; i += NTHREADS) {
        int d = dst16[i];
        int pos = rowptr[d] + atomicAdd(&fill[d], 1);
        csrsrc[pos] = src16[i];
    }
    for (int i = tid; i < 4096; i += NTHREADS) {
        int k = i >> 5, c = i & 31;
        sW[c * 132 + k] = W1[i];
    }
    __syncthreads();

    // ---------------- Phase B: xw1 = dinv * (x @ W1), packed-K, 1 node/warp ----------------
    {
        float* xs = hcat + warp * 132;      // per-warp scratch (hcat unused yet)
        const float* wrow = sW + lane * 132;
        for (int n = warp; n < MNODES; n += NW) {
            float4 xv0 = *(const float4*)(x + (size_t)(nbase + n) * 128 + lane * 4);
            __syncwarp();
            *(float4*)(xs + lane * 4) = xv0;
            __syncwarp();
            u64 acc0 = 0, acc1 = 0;
            #pragma unroll 4
            for (int k = 0; k < 128; k += 4) {
                ulonglong2 hv = *(const ulonglong2*)(xs + k);
                ulonglong2 wv = *(const ulonglong2*)(wrow + k);
                acc0 = fma2(hv.x, wv.x, acc0);
                acc1 = fma2(hv.y, wv.y, acc1);
            }
            float2 a = u2f(add2(acc0, acc1));
            xw[n * 32 + lane] = dinv[n] * (a.x + a.y);
        }
    }
    __syncthreads();

    // ---------------- GCN aggregation layers 1-3 (F=32) ----------------
    const float* Bv[3] = { b1, b2, b3 };
    const float* Wv[2] = { W2, W3 };
    for (int layer = 0; layer < 3; ++layer) {
        int off = layer * 32;
        float2 blv = *(const float2*)(Bv[layer] + 2 * hl);
        // gather: 2 nodes per warp (half-warps), float2 per lane
        const float* xwh = xw + hl * 2;
        for (int p = warp; p < MNODES / 2; p += NW) {
            int node = p * 2 + half;
            int e0 = rowptr[node], e1 = rowptr[node + 1];
            u64 acc0 = *(const u64*)(xw + node * 32 + hl * 2);
            u64 acc1 = 0;
            int e = e0;
            for (; e + 2 <= e1; e += 2) {
                int s0 = csrsrc[e], s1 = csrsrc[e + 1];
                acc0 = add2(acc0, *(const u64*)(xwh + s0 * 32));
                acc1 = add2(acc1, *(const u64*)(xwh + s1 * 32));
            }
            if (e < e1) acc0 = add2(acc0, *(const u64*)(xwh + (int)csrsrc[e] * 32));
            float2 a = u2f(add2(acc0, acc1));
            float dn = dinv[node];
            float* hp = hcat + node * 100 + off + hl * 2;
            hp[0] = fast_tanh(dn * a.x + blv.x);
            hp[1] = fast_tanh(dn * a.y + blv.y);
        }
        if (layer < 2) {
            // stage W^T: sW[c*36 + k]
            for (int i = tid; i < 1024; i += NTHREADS) {
                int k = i >> 5, c = i & 31;
                sW[c * 36 + k] = Wv[layer][i];
            }
            __syncthreads();
            // xw_{l+1} = dinv * (h_l @ W), packed-K
            const float* wrow = sW + lane * 36;
            for (int n = warp; n < MNODES; n += NW) {
                const float* hr = hcat + n * 100 + off;
                u64 acc0 = 0, acc1 = 0;
                #pragma unroll
                for (int k = 0; k < 32; k += 4) {
                    ulonglong2 hv = *(const ulonglong2*)(hr + k);
                    ulonglong2 wv = *(const ulonglong2*)(wrow + k);
                    acc0 = fma2(hv.x, wv.x, acc0);
                    acc1 = fma2(hv.y, wv.y, acc1);
                }
                float2 a = u2f(add2(acc0, acc1));
                xw[n * 32 + lane] = dinv[n] * (a.x + a.y);
            }
            __syncthreads();
        } else {
            __syncthreads();
        }
    }

    // ---------------- Layer 4 (F=1) ----------------
    {
        float w4l = W4[lane];
        for (int n = warp; n < MNODES; n += NW) {
            float v = hcat[n * 100 + 64 + lane] * w4l;
            v = warp_sum(v);
            if (lane == 0) xw[n] = dinv[n] * v;   // xwd4[200]
        }
        __syncthreads();
        float b4v = b4[0];
        for (int n = tid; n < MNODES; n += NTHREADS) {
            float acc = xw[n];
            int e1 = rowptr[n + 1];
            for (int e = rowptr[n]; e < e1; ++e)
                acc += xw[(int)csrsrc[e]];
            float h4 = fast_tanh(dinv[n] * acc + b4v);
            hcat[n * 100 + 96] = h4;
            sKey[n] = h4;
        }
        __syncthreads();
    }

    // ---------------- SortPool: stable top-30 by key desc (warp per node) ----------------
    for (int n = warp; n < MNODES; n += NW) {
        float ki = sKey[n];
        int cnt = 0;
        for (int j = lane; j < MNODES; j += 32) {
            float kj = sKey[j];
            cnt += (kj > ki) || (kj == ki && j < n);
        }
        cnt = __reduce_add_sync(0xffffffffu, cnt);
        if (lane == 0 && cnt < 30) sSel[cnt] = n;
    }
    // stage conv weights into sW
    for (int i = tid; i < 16 * 97; i += NTHREADS) sW[i] = convW1[i];
    for (int i = tid; i < 32 * 16 * 5; i += NTHREADS) sW[1552 + i] = convW2[i];
    __syncthreads();

    // ---------------- Conv1 (kernel 97, stride 97) -> [16][30], relu ----------------
    for (int it = warp; it < 480; it += NW) {
        int p = it / 16, oc = it % 16;
        int node = sSel[p];
        const float* hr = hcat + node * 100;
        const float* wr = sW + oc * 97;
        float v = hr[lane] * wr[lane] + hr[lane + 32] * wr[lane + 32]
                + hr[lane + 64] * wr[lane + 64];
        if (lane == 0) v += hr[96] * wr[96];
        v = warp_sum(v);
        if (lane == 0) sC1[oc * 30 + p] = fmaxf(v + convb1[oc], 0.0f);
    }
    __syncthreads();

    // ---------------- MaxPool1d(2,2) -> [16][15] ----------------
    for (int i = tid; i < 240; i += NTHREADS) {
        int oc = i / 15, t = i % 15;
        sPool[i] = fmaxf(sC1[oc * 30 + 2 * t], sC1[oc * 30 + 2 * t + 1]);
    }
    __syncthreads();

    // ---------------- Conv2 (16->32, k=5) -> [32][11], relu, flatten ----------------
    for (int it = tid; it < 352; it += NTHREADS) {
        int oc = it / 11, t = it % 11;
        float acc = convb2[oc];
        const float* w = sW + 1552 + oc * 80;
        #pragma unroll
        for (int ic = 0; ic < 16; ++ic) {
            #pragma unroll
            for (int k = 0; k < 5; ++k)
                acc += w[ic * 5 + k] * sPool[ic * 15 + t + k];
        }
        sFlat[oc * 11 + t] = fmaxf(acc, 0.0f);
    }
    __syncthreads();

    // ---------------- Linear 352->128 (split-K over 8 groups), relu ----------------
    {
        int grp = tid >> 7, t = tid & 127;
        float acc = 0.0f;
        int f0 = grp * 44, f1 = f0 + 44;
        for (int fi = f0; fi < f1; ++fi)
            acc += sFlat[fi] * linW1[fi * 128 + t];
        sW[grp * 128 + t] = acc;    // sW reused as partial buffer
    }
    __syncthreads();
    if (tid < 128) {
        float a = linb1[tid];
        #pragma unroll
        for (int grp = 0; grp < 8; ++grp) a += sW[grp * 128 + tid];
        sHlin[tid] = fmaxf(a, 0.0f);
    }
    __syncthreads();

    // ---------------- Linear 128->1, sigmoid ----------------
    if (warp == 0) {
        float acc = sHlin[lane] * linW2[lane] + sHlin[lane + 32] * linW2[lane + 32]
                  + sHlin[lane + 64] * linW2[lane + 64] + sHlin[lane + 96] * linW2[lane + 96];
        acc = warp_sum(acc);
        if (lane == 0) {
            float z = acc + linb2[0];
            out[g] = __fdividef(1.0f, 1.0f + __expf(-z));
        }
    }
}

extern "C" void kernel_launch(void* const* d_in, const int* in_sizes, int n_in,
                              void* d_out, int out_size) {
    const float* x      = (const float*)d_in[0];
    const int*   ei     = (const int*)  d_in[1];
    const float* W1     = (const float*)d_in[3];
    const float* b1     = (const float*)d_in[4];
    const float* W2     = (const float*)d_in[5];
    const float* b2     = (const float*)d_in[6];
    const float* W3     = (const float*)d_in[7];
    const float* b3     = (const float*)d_in[8];
    const float* W4     = (const float*)d_in[9];
    const float* b4     = (const float*)d_in[10];
    const float* convW1 = (const float*)d_in[11];
    const float* convb1 = (const float*)d_in[12];
    const float* convW2 = (const float*)d_in[13];
    const float* convb2 = (const float*)d_in[14];
    const float* linW1  = (const float*)d_in[15];
    const float* linb1  = (const float*)d_in[16];
    const float* linW2  = (const float*)d_in[17];
    const float* linb2  = (const float*)d_in[18];
    float* out = (float*)d_out;

    cudaFuncSetAttribute(dgcnn_kernel,
                         cudaFuncAttributeMaxDynamicSharedMemorySize, SMEM_BYTES);
    dgcnn_kernel<<<BGRAPHS, NTHREADS, SMEM_BYTES>>>(
        x, ei, W1, b1, W2, b2, W3, b3, W4, b4,
        convW1, convb1, convW2, convb2, linW1, linb1, linW2, linb2, out);
}

// round 5
// speedup vs baseline: 2.2686x; 1.2772x over previous
#include <cuda_runtime.h>
#include <math.h>

#define BGRAPHS 512
#define MNODES  200
#define EPG     6400
#define ETOT    3276800
#define NTHREADS 1024
#define NW 32

// ---- shared memory layout (float slots) ----
#define OFF_HCAT   0          // 200*100 = 20000 (also x@W1 per-warp scratch early)
#define OFF_XW     20000      // 200*32  = 6400   (holds dinv-scaled xw)
#define OFF_SW     26400      // 4224 weight/scratch staging (W1^T = 32*132)
#define OFF_DINV   30624      // 200
#define OFF_ROWPTR 30824      // 204 ints
#define OFF_FILL   31028      // 200 ints
#define OFF_DEGI   31228      // 200 ints
#define OFF_CSRSRC 31428      // 6400 u16 -> 3200 slots
#define OFF_SRC16  34628      // 6400 u16 -> 3200 slots
#define OFF_DST16  37828      // 6400 u16 -> 3200 slots
#define OFF_KEY    41028      // 200
#define OFF_SEL    41228      // 32 ints
#define OFF_C1     41260      // 480
#define OFF_POOL   41740      // 240
#define OFF_FLAT   41980      // 352
#define OFF_HLIN   42332      // 128
#define SMEM_SLOTS 42460
#define SMEM_BYTES (SMEM_SLOTS * 4)

typedef unsigned long long u64;

__device__ __forceinline__ u64 fma2(u64 a, u64 b, u64 c) {
    u64 d; asm("fma.rn.f32x2 %0,%1,%2,%3;" : "=l"(d) : "l"(a), "l"(b), "l"(c)); return d;
}
__device__ __forceinline__ u64 add2(u64 a, u64 b) {
    u64 d; asm("add.rn.f32x2 %0,%1,%2;" : "=l"(d) : "l"(a), "l"(b)); return d;
}
__device__ __forceinline__ float2 u2f(u64 a) {
    float2 f; asm("mov.b64 {%0,%1},%2;" : "=f"(f.x), "=f"(f.y) : "l"(a)); return f;
}

__device__ __forceinline__ float warp_sum(float v) {
    #pragma unroll
    for (int o = 16; o > 0; o >>= 1) v += __shfl_down_sync(0xffffffffu, v, o);
    return v;
}

__device__ __forceinline__ float fast_tanh(float x) {
    float xc = fminf(fmaxf(x, -15.0f), 15.0f);
    float t = __expf(2.0f * xc);
    return __fdividef(t - 1.0f, t + 1.0f);
}

__global__ __launch_bounds__(NTHREADS, 1)
void dgcnn_kernel(
    const float* __restrict__ x, const int* __restrict__ ei,
    const float* __restrict__ W1, const float* __restrict__ b1,
    const float* __restrict__ W2, const float* __restrict__ b2,
    const float* __restrict__ W3, const float* __restrict__ b3,
    const float* __restrict__ W4, const float* __restrict__ b4,
    const float* __restrict__ convW1, const float* __restrict__ convb1,
    const float* __restrict__ convW2, const float* __restrict__ convb2,
    const float* __restrict__ linW1, const float* __restrict__ linb1,
    const float* __restrict__ linW2, const float* __restrict__ linb2,
    float* __restrict__ out)
{
    extern __shared__ float smem[];
    float* hcat   = smem + OFF_HCAT;    // [200][100]
    float* xw     = smem + OFF_XW;      // [200][32] (dinv-scaled)
    float* sW     = smem + OFF_SW;      // transposed weight staging / scratch
    float* dinv   = smem + OFF_DINV;
    int*   rowptr = (int*)(smem + OFF_ROWPTR);
    int*   fill   = (int*)(smem + OFF_FILL);
    int*   degi   = (int*)(smem + OFF_DEGI);
    unsigned short* csrsrc = (unsigned short*)(smem + OFF_CSRSRC);
    unsigned short* src16  = (unsigned short*)(smem + OFF_SRC16);
    unsigned short* dst16  = (unsigned short*)(smem + OFF_DST16);
    float* sKey   = smem + OFF_KEY;
    int*   sSel   = (int*)(smem + OFF_SEL);
    float* sC1    = smem + OFF_C1;
    float* sPool  = smem + OFF_POOL;
    float* sFlat  = smem + OFF_FLAT;
    float* sHlin  = smem + OFF_HLIN;

    const int g    = blockIdx.x;
    const int tid  = threadIdx.x;
    const int lane = tid & 31;
    const int warp = tid >> 5;
    const int half = lane >> 4;      // 0/1: which node of the pair (gather)
    const int hl   = lane & 15;      // feature-pair index within node
    const int nbase = g * MNODES;
    const long ebase = (long)g * EPG;
    const int* srcg = ei + ebase;
    const int* dstg = ei + (long)ETOT + ebase;

    // ---------------- Phase A: degrees + local edge staging (vectorized) ----------------
    for (int i = tid; i < MNODES; i += NTHREADS) degi[i] = 0;
    __syncthreads();
    for (int i = tid; i < EPG / 4; i += NTHREADS) {
        int4 s4 = ((const int4*)srcg)[i];
        int4 d4 = ((const int4*)dstg)[i];
        ushort4 ss, dd;
        ss.x = (unsigned short)(s4.x - nbase); ss.y = (unsigned short)(s4.y - nbase);
        ss.z = (unsigned short)(s4.z - nbase); ss.w = (unsigned short)(s4.w - nbase);
        dd.x = (unsigned short)(d4.x - nbase); dd.y = (unsigned short)(d4.y - nbase);
        dd.z = (unsigned short)(d4.z - nbase); dd.w = (unsigned short)(d4.w - nbase);
        ((ushort4*)src16)[i] = ss;
        ((ushort4*)dst16)[i] = dd;
        atomicAdd(&degi[dd.x], 1); atomicAdd(&degi[dd.y], 1);
        atomicAdd(&degi[dd.z], 1); atomicAdd(&degi[dd.w], 1);
    }
    __syncthreads();
    for (int i = tid; i < MNODES; i += NTHREADS) {
        dinv[i] = rsqrtf((float)degi[i] + 1.0f);
        fill[i] = 0;
    }
    if (warp == 0) {
        int run = 0;
        #pragma unroll
        for (int c = 0; c < 7; ++c) {
            int i = c * 32 + lane;
            int dv = (i < MNODES) ? degi[i] : 0;
            int v = dv;
            #pragma unroll
            for (int o = 1; o < 32; o <<= 1) {
                int t = __shfl_up_sync(0xffffffffu, v, o);
                if (lane >= o) v += t;
            }
            if (i < MNODES) rowptr[i] = run + v - dv;
            run += __shfl_sync(0xffffffffu, v, 31);
        }
        if (lane == 0) rowptr[MNODES] = EPG;
    }
    __syncthreads();
    // CSR scatter; stage W1^T concurrently: sW[c*132 + k] = W1[k*32 + c]
    for (int i = tid; i < EPG; i += NTHREADS) {
        int d = dst16[i];
        int pos = rowptr[d] + atomicAdd(&fill[d], 1);
        csrsrc[pos] = src16[i];
    }
    for (int i = tid; i < 4096; i += NTHREADS) {
        int k = i >> 5, c = i & 31;
        sW[c * 132 + k] = W1[i];
    }
    __syncthreads();

    // ---------------- Phase B: xw1 = dinv * (x @ W1), 4 nodes per warp ----------------
    {
        float* xs = hcat + warp * 528;      // per-warp scratch: 4 rows * 132
        const float* wrow = sW + lane * 132;
        for (int n0 = warp * 4; n0 < MNODES; n0 += NW * 4) {
            #pragma unroll
            for (int j = 0; j < 4; ++j) {
                float4 v = *(const float4*)(x + (size_t)(nbase + n0 + j) * 128 + lane * 4);
                *(float4*)(xs + j * 132 + lane * 4) = v;
            }
            __syncwarp();
            u64 a00 = 0, a01 = 0, a10 = 0, a11 = 0, a20 = 0, a21 = 0, a30 = 0, a31 = 0;
            #pragma unroll 4
            for (int k = 0; k < 128; k += 4) {
                ulonglong2 wv = *(const ulonglong2*)(wrow + k);
                ulonglong2 h0 = *(const ulonglong2*)(xs + k);
                ulonglong2 h1 = *(const ulonglong2*)(xs + 132 + k);
                ulonglong2 h2 = *(const ulonglong2*)(xs + 264 + k);
                ulonglong2 h3 = *(const ulonglong2*)(xs + 396 + k);
                a00 = fma2(h0.x, wv.x, a00); a01 = fma2(h0.y, wv.y, a01);
                a10 = fma2(h1.x, wv.x, a10); a11 = fma2(h1.y, wv.y, a11);
                a20 = fma2(h2.x, wv.x, a20); a21 = fma2(h2.y, wv.y, a21);
                a30 = fma2(h3.x, wv.x, a30); a31 = fma2(h3.y, wv.y, a31);
            }
            float2 r0 = u2f(add2(a00, a01)); xw[(n0 + 0) * 32 + lane] = dinv[n0 + 0] * (r0.x + r0.y);
            float2 r1 = u2f(add2(a10, a11)); xw[(n0 + 1) * 32 + lane] = dinv[n0 + 1] * (r1.x + r1.y);
            float2 r2 = u2f(add2(a20, a21)); xw[(n0 + 2) * 32 + lane] = dinv[n0 + 2] * (r2.x + r2.y);
            float2 r3 = u2f(add2(a30, a31)); xw[(n0 + 3) * 32 + lane] = dinv[n0 + 3] * (r3.x + r3.y);
            __syncwarp();
        }
    }
    __syncthreads();

    // ---------------- GCN aggregation layers 1-3 (F=32) ----------------
    const float* Bv[3] = { b1, b2, b3 };
    const float* Wv[2] = { W2, W3 };
    for (int layer = 0; layer < 3; ++layer) {
        int off = layer * 32;
        float2 blv = *(const float2*)(Bv[layer] + 2 * hl);
        // gather: 2 nodes per warp (half-warps), float2 per lane, packed idx loads
        const float* xwh = xw + hl * 2;
        for (int p = warp; p < MNODES / 2; p += NW) {
            int node = p * 2 + half;
            int e0 = rowptr[node], e1 = rowptr[node + 1];
            u64 acc0 = *(const u64*)(xw + node * 32 + hl * 2);
            u64 acc1 = 0;
            int e = e0;
            if ((e & 1) && e < e1) {   // align to u32
                acc0 = add2(acc0, *(const u64*)(xwh + (int)csrsrc[e] * 32));
                ++e;
            }
            for (; e + 2 <= e1; e += 2) {
                unsigned pr = *(const unsigned*)(csrsrc + e);
                int s0 = pr & 0xffff, s1 = pr >> 16;
                acc0 = add2(acc0, *(const u64*)(xwh + s0 * 32));
                acc1 = add2(acc1, *(const u64*)(xwh + s1 * 32));
            }
            if (e < e1)
                acc1 = add2(acc1, *(const u64*)(xwh + (int)csrsrc[e] * 32));
            float2 a = u2f(add2(acc0, acc1));
            float dn = dinv[node];
            float* hp = hcat + node * 100 + off + hl * 2;
            hp[0] = fast_tanh(dn * a.x + blv.x);
            hp[1] = fast_tanh(dn * a.y + blv.y);
        }
        if (layer < 2) {
            for (int i = tid; i < 1024; i += NTHREADS) {
                int k = i >> 5, c = i & 31;
                sW[c * 36 + k] = Wv[layer][i];
            }
            __syncthreads();
            // xw_{l+1} = dinv * (h_l @ W), 4 nodes per warp
            const float* wrow = sW + lane * 36;
            for (int n0 = warp * 4; n0 < MNODES; n0 += NW * 4) {
                const float* hr0 = hcat + (n0 + 0) * 100 + off;
                const float* hr1 = hcat + (n0 + 1) * 100 + off;
                const float* hr2 = hcat + (n0 + 2) * 100 + off;
                const float* hr3 = hcat + (n0 + 3) * 100 + off;
                u64 a00 = 0, a01 = 0, a10 = 0, a11 = 0, a20 = 0, a21 = 0, a30 = 0, a31 = 0;
                #pragma unroll
                for (int k = 0; k < 32; k += 4) {
                    ulonglong2 wv = *(const ulonglong2*)(wrow + k);
                    ulonglong2 h0 = *(const ulonglong2*)(hr0 + k);
                    ulonglong2 h1 = *(const ulonglong2*)(hr1 + k);
                    ulonglong2 h2 = *(const ulonglong2*)(hr2 + k);
                    ulonglong2 h3 = *(const ulonglong2*)(hr3 + k);
                    a00 = fma2(h0.x, wv.x, a00); a01 = fma2(h0.y, wv.y, a01);
                    a10 = fma2(h1.x, wv.x, a10); a11 = fma2(h1.y, wv.y, a11);
                    a20 = fma2(h2.x, wv.x, a20); a21 = fma2(h2.y, wv.y, a21);
                    a30 = fma2(h3.x, wv.x, a30); a31 = fma2(h3.y, wv.y, a31);
                }
                float2 r0 = u2f(add2(a00, a01)); xw[(n0 + 0) * 32 + lane] = dinv[n0 + 0] * (r0.x + r0.y);
                float2 r1 = u2f(add2(a10, a11)); xw[(n0 + 1) * 32 + lane] = dinv[n0 + 1] * (r1.x + r1.y);
                float2 r2 = u2f(add2(a20, a21)); xw[(n0 + 2) * 32 + lane] = dinv[n0 + 2] * (r2.x + r2.y);
                float2 r3 = u2f(add2(a30, a31)); xw[(n0 + 3) * 32 + lane] = dinv[n0 + 3] * (r3.x + r3.y);
            }
            __syncthreads();
        } else {
            __syncthreads();
        }
    }

    // ---------------- Layer 4 (F=1) ----------------
    {
        float w4l = W4[lane];
        for (int n = warp; n < MNODES; n += NW) {
            float v = hcat[n * 100 + 64 + lane] * w4l;
            v = warp_sum(v);
            if (lane == 0) xw[n] = dinv[n] * v;   // xwd4[200]
        }
        __syncthreads();
        float b4v = b4[0];
        for (int n = tid; n < MNODES; n += NTHREADS) {
            float acc = xw[n];
            int e1 = rowptr[n + 1];
            for (int e = rowptr[n]; e < e1; ++e)
                acc += xw[(int)csrsrc[e]];
            float h4 = fast_tanh(dinv[n] * acc + b4v);
            hcat[n * 100 + 96] = h4;
            sKey[n] = h4;
        }
        __syncthreads();
    }

    // ---------------- SortPool: stable top-30 by key desc (warp per node) ----------------
    for (int n = warp; n < MNODES; n += NW) {
        float ki = sKey[n];
        int cnt = 0;
        for (int j = lane; j < MNODES; j += 32) {
            float kj = sKey[j];
            cnt += (kj > ki) || (kj == ki && j < n);
        }
        cnt = __reduce_add_sync(0xffffffffu, cnt);
        if (lane == 0 && cnt < 30) sSel[cnt] = n;
    }
    for (int i = tid; i < 16 * 97; i += NTHREADS) sW[i] = convW1[i];
    for (int i = tid; i < 32 * 16 * 5; i += NTHREADS) sW[1552 + i] = convW2[i];
    __syncthreads();

    // ---------------- Conv1 (kernel 97, stride 97) -> [16][30], relu ----------------
    for (int it = warp; it < 480; it += NW) {
        int p = it / 16, oc = it % 16;
        int node = sSel[p];
        const float* hr = hcat + node * 100;
        const float* wr = sW + oc * 97;
        float v = hr[lane] * wr[lane] + hr[lane + 32] * wr[lane + 32]
                + hr[lane + 64] * wr[lane + 64];
        if (lane == 0) v += hr[96] * wr[96];
        v = warp_sum(v);
        if (lane == 0) sC1[oc * 30 + p] = fmaxf(v + convb1[oc], 0.0f);
    }
    __syncthreads();

    // ---------------- MaxPool1d(2,2) -> [16][15] ----------------
    for (int i = tid; i < 240; i += NTHREADS) {
        int oc = i / 15, t = i % 15;
        sPool[i] = fmaxf(sC1[oc * 30 + 2 * t], sC1[oc * 30 + 2 * t + 1]);
    }
    __syncthreads();

    // ---------------- Conv2 (16->32, k=5) -> [32][11], relu, flatten ----------------
    for (int it = tid; it < 352; it += NTHREADS) {
        int oc = it / 11, t = it % 11;
        float acc = convb2[oc];
        const float* w = sW + 1552 + oc * 80;
        #pragma unroll
        for (int ic = 0; ic < 16; ++ic) {
            #pragma unroll
            for (int k = 0; k < 5; ++k)
                acc += w[ic * 5 + k] * sPool[ic * 15 + t + k];
        }
        sFlat[oc * 11 + t] = fmaxf(acc, 0.0f);
    }
    __syncthreads();

    // ---------------- Linear 352->128 (split-K over 8 groups), relu ----------------
    {
        int grp = tid >> 7, t = tid & 127;
        float acc = 0.0f;
        int f0 = grp * 44, f1 = f0 + 44;
        for (int fi = f0; fi < f1; ++fi)
            acc += sFlat[fi] * linW1[fi * 128 + t];
        sW[grp * 128 + t] = acc;
    }
    __syncthreads();
    if (tid < 128) {
        float a = linb1[tid];
        #pragma unroll
        for (int grp = 0; grp < 8; ++grp) a += sW[grp * 128 + tid];
        sHlin[tid] = fmaxf(a, 0.0f);
    }
    __syncthreads();

    // ---------------- Linear 128->1, sigmoid ----------------
    if (warp == 0) {
        float acc = sHlin[lane] * linW2[lane] + sHlin[lane + 32] * linW2[lane + 32]
                  + sHlin[lane + 64] * linW2[lane + 64] + sHlin[lane + 96] * linW2[lane + 96];
        acc = warp_sum(acc);
        if (lane == 0) {
            float z = acc + linb2[0];
            out[g] = __fdividef(1.0f, 1.0f + __expf(-z));
        }
    }
}

extern "C" void kernel_launch(void* const* d_in, const int* in_sizes, int n_in,
                              void* d_out, int out_size) {
    const float* x      = (const float*)d_in[0];
    const int*   ei     = (const int*)  d_in[1];
    const float* W1     = (const float*)d_in[3];
    const float* b1     = (const float*)d_in[4];
    const float* W2     = (const float*)d_in[5];
    const float* b2     = (const float*)d_in[6];
    const float* W3     = (const float*)d_in[7];
    const float* b3     = (const float*)d_in[8];
    const float* W4     = (const float*)d_in[9];
    const float* b4     = (const float*)d_in[10];
    const float* convW1 = (const float*)d_in[11];
    const float* convb1 = (const float*)d_in[12];
    const float* convW2 = (const float*)d_in[13];
    const float* convb2 = (const float*)d_in[14];
    const float* linW1  = (const float*)d_in[15];
    const float* linb1  = (const float*)d_in[16];
    const float* linW2  = (const float*)d_in[17];
    const float* linb2  = (const float*)d_in[18];
    float* out = (float*)d_out;

    cudaFuncSetAttribute(dgcnn_kernel,
                         cudaFuncAttributeMaxDynamicSharedMemorySize, SMEM_BYTES);
    dgcnn_kernel<<<BGRAPHS, NTHREADS, SMEM_BYTES>>>(
        x, ei, W1, b1, W2, b2, W3, b3, W4, b4,
        convW1, convb1, convW2, convb2, linW1, linb1, linW2, linb2, out);
}